// round 14
// baseline (speedup 1.0000x reference)
#include <cuda_runtime.h>
#include <math.h>

// Problem constants
#define B_   128
#define CIN  3
#define COUT 16
#define HW   (256 * 256)          // 65536 elements per plane
#define PLANE_F4 (HW / 4)         // 16384 float4 per plane
#define NPLANES (B_ * CIN)        // 384
#define BLOCKS_PER_PLANE 2
#define THREADS 256
#define NREDUCE (NPLANES * BLOCKS_PER_PLANE)                   // 768 reduce blocks
#define NBLOCKS (NREDUCE + 1)                                  // +1 poller
#define F4_PER_THREAD (PLANE_F4 / BLOCKS_PER_PLANE / THREADS)  // 32

// Scratch (device globals — no allocation allowed).
__device__ float    g_partial[NREDUCE];
__device__ unsigned g_count;   // zero-init; poller resets -> replay-safe

// min 6 CTAs/SM: caps regs ~40 so all 769 CTAs fit in ONE wave
// (6*148=888 >= 769). Epilogue state lives in smem to avoid spills.
__global__ __launch_bounds__(THREADS, 6) void k_all(
    const float4* __restrict__ x,
    const float*  __restrict__ weight,
    const float*  __restrict__ bias,
    float*        __restrict__ out)
{
    const int t = threadIdx.x;

    if (blockIdx.x == NREDUCE) {
        // ================= poller / epilogue block =================
        // Independent prep first (overlaps the reducing blocks).
        __shared__ float wsum[CIN][COUT];
        __shared__ float sbias[COUT];
        if (t < CIN * COUT) {
            int ci = t / COUT, co = t % COUT;
            float acc = 0.0f;
            #pragma unroll
            for (int pq = 0; pq < 9; pq++)
                acc += weight[(ci * COUT + co) * 9 + pq];
            wsum[ci][co] = acc;
        }
        if (t < COUT) sbias[t] = bias[t];
        __syncthreads();

        // Spin until all reduce blocks published (acquire pairs with
        // reducers' red.release).
        __shared__ unsigned s_done;
        if (t == 0) {
            unsigned c;
            do {
                asm volatile("ld.acquire.gpu.global.u32 %0, [%1];"
                             : "=r"(c) : "l"(&g_count));
            } while (c < (unsigned)NREDUCE);
            s_done = 1;
        }
        __syncthreads();
        (void)s_done;

        if (t < B_) {
            // 6 partials at g_partial[t*6]; pair-starts even -> 8B-aligned.
            const float2 pa = *reinterpret_cast<const float2*>(&g_partial[t * 6 + 0]);
            const float2 pb = *reinterpret_cast<const float2*>(&g_partial[t * 6 + 2]);
            const float2 pc = *reinterpret_cast<const float2*>(&g_partial[t * 6 + 4]);
            const float s0 = pa.x + pa.y;
            const float s1 = pb.x + pb.y;
            const float s2 = pc.x + pc.y;
            const float inv = 1.0f / (258.0f * 258.0f);

            float m = -INFINITY;
            float y[COUT];
            #pragma unroll
            for (int co = 0; co < COUT; co++) {
                float v = (s0 * wsum[0][co] + s1 * wsum[1][co] + s2 * wsum[2][co]) * inv
                          + sbias[co];
                y[co] = v;
                m = fmaxf(m, v);
            }
            float e = 0.0f;
            #pragma unroll
            for (int co = 0; co < COUT; co++)
                e += expf(y[co] - m);

            out[t] = 10.0f * (m + logf(e));
        }
        if (t == 0) g_count = 0;   // reset for next graph replay
        return;
    }

    // ================= reduce blocks =================
    const int plane = blockIdx.x >> 1;
    const int chunk = blockIdx.x & 1;
    const float4* base = x + (size_t)plane * PLANE_F4
                           + (size_t)chunk * (PLANE_F4 / BLOCKS_PER_PLANE);

    float s = 0.0f;
    #pragma unroll 16
    for (int i = 0; i < F4_PER_THREAD; i++) {
        float4 v = base[t + i * THREADS];
        s += (v.x + v.y) + (v.z + v.w);
    }

    // warp reduce
    #pragma unroll
    for (int o = 16; o > 0; o >>= 1)
        s += __shfl_xor_sync(0xFFFFFFFFu, s, o);

    __shared__ float ws[THREADS / 32];
    if ((t & 31) == 0) ws[t >> 5] = s;
    __syncthreads();

    if (t == 0) {
        float acc = 0.0f;
        #pragma unroll
        for (int w = 0; w < THREADS / 32; w++) acc += ws[w];
        g_partial[blockIdx.x] = acc;
        // Publish with release semantics (orders the partial store;
        // no full membar, no L1 flush).
        asm volatile("red.release.gpu.global.add.u32 [%0], 1;"
                     :: "l"(&g_count) : "memory");
    }
}

extern "C" void kernel_launch(void* const* d_in, const int* in_sizes, int n_in,
                              void* d_out, int out_size) {
    const float4* x      = (const float4*)d_in[0];
    const float*  weight = (const float*)d_in[1];
    const float*  bias   = (const float*)d_in[2];
    float* out = (float*)d_out;

    k_all<<<NBLOCKS, THREADS>>>(x, weight, bias, out);
}